// round 11
// baseline (speedup 1.0000x reference)
#include <cuda_runtime.h>

#define BB 4
#define NN 8
#define HH 48
#define WW 48
#define HW (HH*WW)        /* 2304 */
#define HW2 (HW/2)        /* 1152 float2 */
#define TH 12
#define SMH (TH+6)        /* 18 */
#define SMW (WW+6)        /* 54 */
#define SFN (SMH*SMW)     /* 972 */
#define NTHR 288
#define OUT_I_ELEMS (BB*NN*3*HW)   /* 221184 */
#define OUTM_ELEMS (BB*3*HW)       /* 27648  */
#define ZERO_TOT ((OUT_I_ELEMS + OUTM_ELEMS)/4)

// Zero out_i + out_m (both atomically accumulated).
__global__ void zero_kernel(float4* __restrict__ p)
{
    int i = blockIdx.x * blockDim.x + threadIdx.x;
    if (i < ZERO_TOT) p[i] = make_float4(0.f, 0.f, 0.f, 0.f);
}

// Decomposed rank-1 kernel-prediction apply, 2 pixels per thread (float2).
// One block = (12-row tile, color c, RGB t, n, b). Computes the partial
//   r = sum_s W[b,n,s,t] * S^c_{K(s)},  K(s)=7,5,3,1
//   S^c_K = sum_k c1[cur+k,c,t] * sum_l c2[cur+l,c,t] * F[c, h+k-3, w+l-3]
// and accumulates 0.25*r into pred_img_i and r/32 into pred_img (atomics).
__global__ __launch_bounds__(NTHR, 2)
void kpn_kernel(const float* __restrict__ frames,
                const float* __restrict__ core,
                const float* __restrict__ kw,
                float* __restrict__ out_i,
                float* __restrict__ out_m)
{
    const int tile = blockIdx.x / 12;
    const int ct   = blockIdx.x - tile*12;
    const int c    = ct & 3;
    const int t    = ct >> 2;
    const int n    = blockIdx.y;
    const int b    = blockIdx.z;
    const int h0   = tile * TH;

    __shared__ float sF[SMH][SMW];

    const int tid = threadIdx.x;
    const int ti  = tid / 24;            // 0..11 (row in tile)
    const int w0  = 2*(tid - ti*24);     // even column 0..46
    const int p2  = h0*24 + tid;         // float2 index of this pixel pair

    // ---- core: 32 float2 LDGs (256B/warp each), batched up front ----
    // channel (within b,n): ch = q*12 + c*3 + t, stride HW floats
    const float2* cb2 = (const float2*)core
                      + ((size_t)b*3072 + (size_t)n*384 + (size_t)(c*3 + t))*HW2
                      + p2;
    float2 c1v[16], c2v[16];
    #pragma unroll
    for (int q = 0; q < 16; q++) {
        c1v[q] = cb2[(size_t)( q     *12) * HW2];
        c2v[q] = cb2[(size_t)((16+q)*12) * HW2];
    }

    // kernel_weight[b][n][s][t][h][w]; s=0 pairs with K=7 (KS[::-1] stack)
    const float2* wb2 = (const float2*)kw
                      + ((size_t)(b*NN + n))*12*HW2 + (size_t)t*HW2 + p2;
    float2 wb[4];
    #pragma unroll
    for (int s = 0; s < 4; s++)
        wb[s] = wb2[(size_t)(s*3) * HW2];

    // ---- frames tile for color c (halo 3), prefetched into regs ----
    const float* fbase = frames + ((size_t)((b*NN + n)*4 + c)) * HW;
    float fv[4];
    #pragma unroll
    for (int k = 0; k < 4; k++) {
        int idx = k*NTHR + tid;
        float v = 0.f;
        if (idx < SFN) {
            int i  = idx / SMW;
            int j  = idx - i*SMW;
            int hh = h0 + i - 3;
            int wp = j - 3;
            if ((unsigned)hh < HH && (unsigned)wp < WW)
                v = fbase[hh*WW + wp];
        }
        fv[k] = v;
    }
    #pragma unroll
    for (int k = 0; k < 4; k++) {
        int idx = k*NTHR + tid;
        if (idx < SFN) (&sF[0][0])[idx] = fv[k];
    }
    __syncthreads();

    // ---- 7-row walk; row i feeds K7 always, K5 rows 1..5, K3 rows 2..4,
    //      K1 row 3. Two adjacent pixels share the 8-float window. ----
    float2 a0 = {0.f,0.f}, a1 = {0.f,0.f}, a2 = {0.f,0.f}, a3 = {0.f,0.f};
    #pragma unroll
    for (int i = 0; i < 7; i++) {
        float v[8];
        #pragma unroll
        for (int m = 0; m < 4; m++) {
            float2 vv = *(const float2*)&sF[ti + i][w0 + 2*m];  // LDS.64
            v[2*m]   = vv.x;
            v[2*m+1] = vv.y;
        }

        float rs7a = 0.f, rs7b = 0.f;
        #pragma unroll
        for (int l = 0; l < 7; l++) {
            rs7a += c2v[9 + l].x * v[l];
            rs7b += c2v[9 + l].y * v[l + 1];
        }
        a3.x += c1v[9 + i].x * rs7a;
        a3.y += c1v[9 + i].y * rs7b;

        if (i >= 1 && i <= 5) {
            float rs5a = 0.f, rs5b = 0.f;
            #pragma unroll
            for (int l = 0; l < 5; l++) {
                rs5a += c2v[4 + l].x * v[1 + l];
                rs5b += c2v[4 + l].y * v[2 + l];
            }
            a2.x += c1v[4 + (i-1)].x * rs5a;
            a2.y += c1v[4 + (i-1)].y * rs5b;
        }
        if (i >= 2 && i <= 4) {
            float rs3a = c2v[1].x*v[2] + c2v[2].x*v[3] + c2v[3].x*v[4];
            float rs3b = c2v[1].y*v[3] + c2v[2].y*v[4] + c2v[3].y*v[5];
            a1.x += c1v[1 + (i-2)].x * rs3a;
            a1.y += c1v[1 + (i-2)].y * rs3b;
        }
        if (i == 3) {
            a0.x += c1v[0].x * (c2v[0].x * v[3]);
            a0.y += c1v[0].y * (c2v[0].y * v[4]);
        }
    }

    float2 r;
    r.x = wb[0].x*a3.x + wb[1].x*a2.x + wb[2].x*a1.x + wb[3].x*a0.x;
    r.y = wb[0].y*a3.y + wb[1].y*a2.y + wb[2].y*a1.y + wb[3].y*a0.y;

    float2* oi = (float2*)out_i + ((size_t)(b*NN + n))*3*HW2 + (size_t)t*HW2 + p2;
    float2* om = (float2*)out_m + (size_t)b*3*HW2 + (size_t)t*HW2 + p2;
    atomicAdd(oi, make_float2(0.25f*r.x, 0.25f*r.y));
    atomicAdd(om, make_float2(0.03125f*r.x, 0.03125f*r.y));  // 0.25/8
}

extern "C" void kernel_launch(void* const* d_in, const int* in_sizes, int n_in,
                              void* d_out, int out_size)
{
    const float* frames = (const float*)d_in[0];
    const float* core   = (const float*)d_in[1];
    const float* kw     = (const float*)d_in[2];

    float* out   = (float*)d_out;
    float* out_i = out;                    // pred_img_i: (4,8,3,48,48)
    float* out_m = out + OUT_I_ELEMS;      // pred_img:   (4,3,48,48)

    zero_kernel<<<(ZERO_TOT + 255)/256, 256>>>((float4*)out);

    dim3 grid((HH/TH)*12, NN, BB);         // 48 x 8 x 4 = 1536 blocks
    kpn_kernel<<<grid, NTHR>>>(frames, core, kw, out_i, out_m);
}

// round 12
// speedup vs baseline: 1.0206x; 1.0206x over previous
#include <cuda_runtime.h>

#define BB 4
#define NN 8
#define HH 48
#define WW 48
#define HW (HH*WW)        /* 2304 */
#define HW2 (HW/2)        /* 1152 float2 */
#define TH 12
#define SMH (TH+6)        /* 18 */
#define SMW (WW+6)        /* 54 */
#define SFN (SMH*SMW)     /* 972 */
#define NTHR 288
#define OUT_I_ELEMS (BB*NN*3*HW)   /* 221184 */
#define OUTM_ELEMS (BB*3*HW)       /* 27648  */
#define ZERO_TOT ((OUT_I_ELEMS + OUTM_ELEMS)/4)

// Zero out_i + out_m, then fire the PDL trigger so the main kernel's
// dependency resolves the moment the stores are done.
__global__ void zero_kernel(float4* __restrict__ p)
{
    int i = blockIdx.x * blockDim.x + threadIdx.x;
    if (i < ZERO_TOT) p[i] = make_float4(0.f, 0.f, 0.f, 0.f);
#if __CUDA_ARCH__ >= 900
    cudaTriggerProgrammaticLaunchCompletion();
#endif
}

// Decomposed rank-1 kernel-prediction apply, 2 pixels per thread (float2).
// One block = (12-row tile, color c, RGB t, n, b). Computes the partial
//   r = sum_s W[b,n,s,t] * S^c_{K(s)},  K(s)=7,5,3,1
//   S^c_K = sum_k c1[cur+k,c,t] * sum_l c2[cur+l,c,t] * F[c, h+k-3, w+l-3]
// and accumulates 0.25*r into pred_img_i and r/32 into pred_img (atomics).
// Launched with PDL: all loads/compute overlap the zeroing kernel; we only
// griddep-sync immediately before the first atomic.
__global__ __launch_bounds__(NTHR, 2)
void kpn_kernel(const float* __restrict__ frames,
                const float* __restrict__ core,
                const float* __restrict__ kw,
                float* __restrict__ out_i,
                float* __restrict__ out_m)
{
    const int tile = blockIdx.x / 12;
    const int ct   = blockIdx.x - tile*12;
    const int c    = ct & 3;
    const int t    = ct >> 2;
    const int n    = blockIdx.y;
    const int b    = blockIdx.z;
    const int h0   = tile * TH;

    __shared__ float sF[SMH][SMW];

    const int tid = threadIdx.x;
    const int ti  = tid / 24;            // 0..11 (row in tile)
    const int w0  = 2*(tid - ti*24);     // even column 0..46
    const int p2  = h0*24 + tid;         // float2 index of this pixel pair

    // ---- core: 32 float2 LDGs (evict-first: read exactly once) ----
    // channel (within b,n): ch = q*12 + c*3 + t, stride HW floats
    const float2* cb2 = (const float2*)core
                      + ((size_t)b*3072 + (size_t)n*384 + (size_t)(c*3 + t))*HW2
                      + p2;
    float2 c1v[16], c2v[16];
    #pragma unroll
    for (int q = 0; q < 16; q++) {
        c1v[q] = __ldcs(&cb2[(size_t)( q    *12) * HW2]);
        c2v[q] = __ldcs(&cb2[(size_t)((16+q)*12) * HW2]);
    }

    // kernel_weight[b][n][s][t][h][w]; s=0 pairs with K=7 (KS[::-1] stack)
    const float2* wb2 = (const float2*)kw
                      + ((size_t)(b*NN + n))*12*HW2 + (size_t)t*HW2 + p2;
    float2 wb[4];
    #pragma unroll
    for (int s = 0; s < 4; s++)
        wb[s] = wb2[(size_t)(s*3) * HW2];

    // ---- frames tile for color c (halo 3), prefetched into regs ----
    const float* fbase = frames + ((size_t)((b*NN + n)*4 + c)) * HW;
    float fv[4];
    #pragma unroll
    for (int k = 0; k < 4; k++) {
        int idx = k*NTHR + tid;
        float v = 0.f;
        if (idx < SFN) {
            int i  = idx / SMW;
            int j  = idx - i*SMW;
            int hh = h0 + i - 3;
            int wp = j - 3;
            if ((unsigned)hh < HH && (unsigned)wp < WW)
                v = fbase[hh*WW + wp];
        }
        fv[k] = v;
    }
    #pragma unroll
    for (int k = 0; k < 4; k++) {
        int idx = k*NTHR + tid;
        if (idx < SFN) (&sF[0][0])[idx] = fv[k];
    }
    __syncthreads();

    // ---- 7-row walk; row i feeds K7 always, K5 rows 1..5, K3 rows 2..4,
    //      K1 row 3. Two adjacent pixels share the 8-float window. ----
    float2 a0 = {0.f,0.f}, a1 = {0.f,0.f}, a2 = {0.f,0.f}, a3 = {0.f,0.f};
    #pragma unroll
    for (int i = 0; i < 7; i++) {
        float v[8];
        #pragma unroll
        for (int m = 0; m < 4; m++) {
            float2 vv = *(const float2*)&sF[ti + i][w0 + 2*m];  // LDS.64
            v[2*m]   = vv.x;
            v[2*m+1] = vv.y;
        }

        float rs7a = 0.f, rs7b = 0.f;
        #pragma unroll
        for (int l = 0; l < 7; l++) {
            rs7a += c2v[9 + l].x * v[l];
            rs7b += c2v[9 + l].y * v[l + 1];
        }
        a3.x += c1v[9 + i].x * rs7a;
        a3.y += c1v[9 + i].y * rs7b;

        if (i >= 1 && i <= 5) {
            float rs5a = 0.f, rs5b = 0.f;
            #pragma unroll
            for (int l = 0; l < 5; l++) {
                rs5a += c2v[4 + l].x * v[1 + l];
                rs5b += c2v[4 + l].y * v[2 + l];
            }
            a2.x += c1v[4 + (i-1)].x * rs5a;
            a2.y += c1v[4 + (i-1)].y * rs5b;
        }
        if (i >= 2 && i <= 4) {
            float rs3a = c2v[1].x*v[2] + c2v[2].x*v[3] + c2v[3].x*v[4];
            float rs3b = c2v[1].y*v[3] + c2v[2].y*v[4] + c2v[3].y*v[5];
            a1.x += c1v[1 + (i-2)].x * rs3a;
            a1.y += c1v[1 + (i-2)].y * rs3b;
        }
        if (i == 3) {
            a0.x += c1v[0].x * (c2v[0].x * v[3]);
            a0.y += c1v[0].y * (c2v[0].y * v[4]);
        }
    }

    float2 r;
    r.x = wb[0].x*a3.x + wb[1].x*a2.x + wb[2].x*a1.x + wb[3].x*a0.x;
    r.y = wb[0].y*a3.y + wb[1].y*a2.y + wb[2].y*a1.y + wb[3].y*a0.y;

#if __CUDA_ARCH__ >= 900
    cudaGridDependencySynchronize();     // zero_kernel done; safe to accumulate
#endif

    float2* oi = (float2*)out_i + ((size_t)(b*NN + n))*3*HW2 + (size_t)t*HW2 + p2;
    float2* om = (float2*)out_m + (size_t)b*3*HW2 + (size_t)t*HW2 + p2;
    atomicAdd(oi, make_float2(0.25f*r.x, 0.25f*r.y));
    atomicAdd(om, make_float2(0.03125f*r.x, 0.03125f*r.y));  // 0.25/8
}

extern "C" void kernel_launch(void* const* d_in, const int* in_sizes, int n_in,
                              void* d_out, int out_size)
{
    const float* frames = (const float*)d_in[0];
    const float* core   = (const float*)d_in[1];
    const float* kw     = (const float*)d_in[2];

    float* out   = (float*)d_out;
    float* out_i = out;                    // pred_img_i: (4,8,3,48,48)
    float* out_m = out + OUT_I_ELEMS;      // pred_img:   (4,3,48,48)

    zero_kernel<<<(ZERO_TOT + 255)/256, 256>>>((float4*)out);

    // PDL launch: kpn may begin while zero_kernel runs; it synchronizes on
    // the trigger only right before its atomics.
    cudaLaunchConfig_t cfg = {};
    cfg.gridDim  = dim3((HH/TH)*12, NN, BB);   // 48 x 8 x 4 = 1536 blocks
    cfg.blockDim = dim3(NTHR, 1, 1);
    cfg.dynamicSmemBytes = 0;
    cudaLaunchAttribute attrs[1];
    attrs[0].id = cudaLaunchAttributeProgrammaticStreamSerialization;
    attrs[0].val.programmaticStreamSerializationAllowed = 1;
    cfg.attrs = attrs;
    cfg.numAttrs = 1;

    cudaLaunchKernelEx(&cfg, kpn_kernel, frames, core, kw, out_i, out_m);
}